// round 1
// baseline (speedup 1.0000x reference)
#include <cuda_runtime.h>
#include <cstdint>

// ---------------------------------------------------------------------------
// TTM recurrence, GB300. Key facts:
//  - softmax over a singleton axis == 1  => Wq/Wk are never needed.
//  - 96 strictly-sequential iterations of matvecs (batch=1): HBM-bound.
//  - One persistent kernel (148 blocks x 512 thr, 1 block/SM co-resident),
//    custom sense-reversing grid barrier (count per launch is EVEN -> state
//    self-resets to zero, graph-replay safe).
//  - vcum double-buffered by token parity (read old buf, write other buf).
// ---------------------------------------------------------------------------

#define NBLK   148
#define NTHR   512
#define NWB    16            // warps per block
#define NWARPS (NBLK * NWB)  // 2368
#define MDIM   2048
#define HDIM   8192
#define NAVG   32
#define NTK    3

__device__ float g_xcfT[MDIM * NAVG];      // xcf transposed: [m][i]
__device__ float g_s0[NAVG * MDIM];        // token initial states
__device__ float g_s[MDIM];                // current activation
__device__ float g_s1[MDIM];               // post-Wo activation
__device__ float g_v[MDIM];                // v vector
__device__ float g_h[HDIM];                // mlp hidden
__device__ float g_vcum[2][NTK][MDIM];     // double-buffered vcum
__device__ int            g_cnt;           // barrier counter (starts 0)
__device__ volatile int   g_sense;         // barrier sense (starts 0)

// --------------------------- grid barrier ----------------------------------
__device__ __forceinline__ void grid_sync(int* lsense) {
    __syncthreads();
    if (threadIdx.x == 0) {
        int s = 1 - *lsense;
        *lsense = s;
        __threadfence();
        if (atomicAdd(&g_cnt, 1) == NBLK - 1) {
            atomicExch(&g_cnt, 0);
            __threadfence();
            g_sense = s;
        } else {
            while (g_sense != s) { __nanosleep(64); }
        }
        __threadfence();
    }
    __syncthreads();
}

// --------------------------- block reduction -------------------------------
__device__ __forceinline__ float blk_sum(float v) {
    __shared__ float red[16];
    #pragma unroll
    for (int o = 16; o; o >>= 1) v += __shfl_xor_sync(0xffffffffu, v, o);
    int w = threadIdx.x >> 5, l = threadIdx.x & 31;
    if (l == 0) red[w] = v;
    __syncthreads();
    float r;
    if (threadIdx.x < 32) {
        float t = (l < NWB) ? red[l] : 0.f;
        #pragma unroll
        for (int o = 8; o; o >>= 1) t += __shfl_xor_sync(0xffffffffu, t, o);
        if (l == 0) red[0] = t;
    }
    __syncthreads();
    r = red[0];
    __syncthreads();
    return r;
}

// stage dst_smem[m] = LN(src)[m] (+ src[m] if addres). Two-pass, exact.
__device__ __forceinline__ void stage_ln(const float* __restrict__ src,
                                         const float* __restrict__ gma,
                                         const float* __restrict__ bta,
                                         float* __restrict__ dst,
                                         bool addres) {
    float vals[4];
    float s = 0.f;
    #pragma unroll
    for (int k = 0; k < 4; k++) {
        vals[k] = src[threadIdx.x + k * NTHR];
        s += vals[k];
    }
    float mean = blk_sum(s) * (1.f / (float)MDIM);
    float q = 0.f;
    #pragma unroll
    for (int k = 0; k < 4; k++) {
        float d = vals[k] - mean;
        q += d * d;
    }
    float var  = blk_sum(q) * (1.f / (float)MDIM);
    float rstd = rsqrtf(var + 1e-5f);
    #pragma unroll
    for (int k = 0; k < 4; k++) {
        int m = threadIdx.x + k * NTHR;
        float xn = (vals[k] - mean) * rstd * gma[m] + bta[m];
        dst[m] = addres ? (xn + vals[k]) : xn;
    }
    __syncthreads();
}

// warp dot-product: row of K=NV4*4 floats vs smem vector. 4 accumulators.
template <int NV4>
__device__ __forceinline__ float warp_dot(const float* __restrict__ w,
                                          const float* __restrict__ xs,
                                          int lane) {
    const float4* w4 = reinterpret_cast<const float4*>(w);
    const float4* x4 = reinterpret_cast<const float4*>(xs);
    float a0 = 0.f, a1 = 0.f, a2 = 0.f, a3 = 0.f;
    #pragma unroll
    for (int j = 0; j < NV4 / 128; j++) {
        int base = lane + j * 128;
        float4 wa = w4[base],      xa = x4[base];
        float4 wb = w4[base + 32], xb = x4[base + 32];
        float4 wc = w4[base + 64], xc = x4[base + 64];
        float4 wd = w4[base + 96], xd = x4[base + 96];
        a0 += wa.x * xa.x + wa.y * xa.y + wa.z * xa.z + wa.w * xa.w;
        a1 += wb.x * xb.x + wb.y * xb.y + wb.z * xb.z + wb.w * xb.w;
        a2 += wc.x * xc.x + wc.y * xc.y + wc.z * xc.z + wc.w * xc.w;
        a3 += wd.x * xd.x + wd.y * xd.y + wd.z * xd.z + wd.w * xd.w;
    }
    float acc = (a0 + a1) + (a2 + a3);
    #pragma unroll
    for (int o = 16; o; o >>= 1) acc += __shfl_xor_sync(0xffffffffu, acc, o);
    return acc;
}

__global__ void __launch_bounds__(NTHR, 1)
ttm_persistent(const float* __restrict__ x,
               const float* __restrict__ weight,
               const float* __restrict__ Wv,
               const float* __restrict__ Wo,
               const float* __restrict__ ln1_g, const float* __restrict__ ln1_b,
               const float* __restrict__ ln2_g, const float* __restrict__ ln2_b,
               const float* __restrict__ fc1_w, const float* __restrict__ fc1_b,
               const float* __restrict__ fc2_w, const float* __restrict__ fc2_b,
               float* __restrict__ out) {
    __shared__ __align__(16) float sm[8448];   // max(8448 prologue, 8192 h-stage)
    const int tid  = threadIdx.x;
    const int lane = tid & 31;
    const int wid  = tid >> 5;
    const int gw   = blockIdx.x * NWB + wid;   // global warp id
    int lsense = 0;

    // zero vcum read-buffers (every launch; state is dirty after prior launch)
    for (int g = blockIdx.x * NTHR + tid; g < 2 * NTK * MDIM; g += NBLK * NTHR)
        (&g_vcum[0][0][0])[g] = 0.f;

    // ---- Phase A: segment-average x -> xcfT[m][i] ----
    // g = a*4096 + b*32 + i ; value = mean_{t in [i*16,(i+1)*16)} x[a][b][t]
    for (int g = blockIdx.x * NTHR + tid; g < NAVG * MDIM; g += NBLK * NTHR) {
        int i = g & 31;
        int b = (g >> 5) & 127;
        int a = g >> 12;
        const float* p = x + (size_t)a * (128 * 512) + (size_t)b * 512 + i * 16;
        float ssum = 0.f;
        #pragma unroll
        for (int k = 0; k < 16; k++) ssum += p[k];
        g_xcfT[(b * 16 + a) * 32 + i] = ssum * (1.f / 16.f);
    }
    grid_sync(&lsense);   // barrier 1

    // ---- Phase B: s0[i][r] = sum_m xcf[i][m]*weight[r][m] + bias[i][r] ----
    {
        const int  row = gw;
        const bool has = row < MDIM;
        float acc[32];
        #pragma unroll
        for (int ii = 0; ii < 32; ii++) acc[ii] = 0.f;
        for (int c = 0; c < 8; c++) {              // 8 chunks of 256 m-values
            for (int idx = tid; idx < 8192; idx += NTHR) {
                int mm = idx >> 5, ii = idx & 31;
                sm[mm * 33 + ii] = g_xcfT[(c * 256 + mm) * 32 + ii];
            }
            __syncthreads();
            if (has) {
                const float* wr = weight + (size_t)row * MDIM + c * 256;
                for (int mm = lane; mm < 256; mm += 32) {
                    float w = wr[mm];
                    #pragma unroll
                    for (int ii = 0; ii < 32; ii++)
                        acc[ii] = fmaf(w, sm[mm * 33 + ii], acc[ii]);
                }
            }
            __syncthreads();
        }
        if (has) {
            float myval = 0.f;
            #pragma unroll
            for (int ii = 0; ii < 32; ii++) {
                float v = acc[ii];
                #pragma unroll
                for (int o = 16; o; o >>= 1) v += __shfl_xor_sync(0xffffffffu, v, o);
                if (lane == ii) myval = v;     // lane l keeps token-l result
            }
            // sinusoidal bias: t = row/2; ang = i * 10000^(-t/512)
            int   t    = row >> 1;
            float freq = expf(-(float)t * (4.f / 2048.f) * 9.210340371976184f);
            float ang  = (float)lane * freq;
            float bias = (row & 1) ? cosf(ang) : sinf(ang);
            g_s0[(size_t)lane * MDIM + row] = myval + bias;
        }
    }
    grid_sync(&lsense);   // barrier 2

    // ---- main recurrence: 32 tokens x 3 layers, 4 grid syncs each ----
    for (int i = 0; i < NAVG; i++) {
        const int prd = i & 1, pwr = prd ^ 1;
        for (int a = 0; a < NTK; a++) {
            const float* cur_s = (a == 0) ? (g_s0 + (size_t)i * MDIM) : g_s;

            // P0: xn = LN1(s) (staged in smem); v = Wv[a] @ xn
            stage_ln(cur_s, ln1_g, ln1_b, sm, false);
            if (gw < MDIM) {
                const float* W = Wv + ((size_t)a * MDIM + gw) * MDIM;
                float d = warp_dot<512>(W, sm, lane);
                if (lane == 0) g_v[gw] = d;
            }
            grid_sync(&lsense);

            // P1: u = vcum_old[a] + v (staged); s1 = Wo[a] @ u + s;
            //     block0 writes vcum_new[a] = u
            for (int m = tid; m < MDIM; m += NTHR)
                sm[m] = g_vcum[prd][a][m] + g_v[m];
            __syncthreads();
            if (blockIdx.x == 0)
                for (int m = tid; m < MDIM; m += NTHR) g_vcum[pwr][a][m] = sm[m];
            if (gw < MDIM) {
                const float* W = Wo + ((size_t)a * MDIM + gw) * MDIM;
                float d = warp_dot<512>(W, sm, lane);
                if (lane == 0) g_s1[gw] = d + cur_s[gw];
            }
            grid_sync(&lsense);

            // P2: s2 = LN2(s1)+s1 (staged); h = gelu(fc1 @ s2 + b1)
            stage_ln(g_s1, ln2_g, ln2_b, sm, true);
            for (int r = gw; r < HDIM; r += NWARPS) {
                float d = warp_dot<512>(fc1_w + (size_t)r * MDIM, sm, lane);
                if (lane == 0) {
                    float xv = d + fc1_b[r];
                    g_h[r] = 0.5f * xv * (1.f + erff(xv * 0.7071067811865476f));
                }
            }
            grid_sync(&lsense);

            // P3: stage h (32KB smem); s = fc2 @ h + b2; emit output at a==2
            for (int m = tid; m < HDIM; m += NTHR) sm[m] = g_h[m];
            __syncthreads();
            if (gw < MDIM) {
                float d = warp_dot<2048>(fc2_w + (size_t)gw * HDIM, sm, lane);
                if (lane == 0) {
                    float val = d + fc2_b[gw];
                    g_s[gw] = val;
                    if (a == NTK - 1) out[(size_t)i * MDIM + gw] = val;
                }
            }
            grid_sync(&lsense);
        }
    }
    // total barriers: 2 + 32*3*4 = 386 (EVEN) -> g_sense/g_cnt end at 0.
}

extern "C" void kernel_launch(void* const* d_in, const int* in_sizes, int n_in,
                              void* d_out, int out_size) {
    (void)in_sizes; (void)n_in; (void)out_size;
    const float* x      = (const float*)d_in[0];
    const float* weight = (const float*)d_in[1];
    // d_in[2] = Wq, d_in[3] = Wk : mathematically dead (softmax over scalar == 1)
    const float* Wv     = (const float*)d_in[4];
    const float* Wo     = (const float*)d_in[5];
    const float* ln1_g  = (const float*)d_in[6];
    const float* ln1_b  = (const float*)d_in[7];
    const float* ln2_g  = (const float*)d_in[8];
    const float* ln2_b  = (const float*)d_in[9];
    const float* fc1_w  = (const float*)d_in[10];
    const float* fc1_b  = (const float*)d_in[11];
    const float* fc2_w  = (const float*)d_in[12];
    const float* fc2_b  = (const float*)d_in[13];

    ttm_persistent<<<NBLK, NTHR>>>(x, weight, Wv, Wo,
                                   ln1_g, ln1_b, ln2_g, ln2_b,
                                   fc1_w, fc1_b, fc2_w, fc2_b,
                                   (float*)d_out);
}

// round 2
// speedup vs baseline: 1.9207x; 1.9207x over previous
#include <cuda_runtime.h>
#include <cstdint>

// ---------------------------------------------------------------------------
// TTM recurrence, GB300 — wavefront-pipelined persistent kernel.
//  - softmax over singleton axis == 1  => Wq/Wk dead.
//  - (token i, layer a) depends only on (i-1,a) [vcum] and (i,a-1) [s]
//    => wavefront: stage s = i + a, 34 stages, <=3 pairs/stage.
//  - fc1/fc2 shared across layers: stream once per stage, dot vs 3 vectors
//    => DRAM traffic 15.4 GB -> 7.6 GB; barriers 386 -> 138 (even, self-reset).
// ---------------------------------------------------------------------------

#define NBLK   148
#define NTHR   512
#define NWB    16
#define NWARPS (NBLK * NWB)   // 2368
#define MDIM   2048
#define HDIM   8192
#define NAVG   32
#define NTK    3
#define NST    (NAVG + NTK - 1)   // 34 stages

__device__ float g_xcfT[MDIM * NAVG];
__device__ float g_s0[NAVG * MDIM];
__device__ float g_sbuf[2][NTK][MDIM];   // s entering layer a, parity-buffered
__device__ float g_s1[NTK][MDIM];        // post-Wo (per active slot k)
__device__ float g_vv[NTK][MDIM];        // v vectors (per slot k)
__device__ float g_hh[NTK][HDIM];        // mlp hidden (per slot k)
__device__ float g_vcum[2][NTK][MDIM];   // parity-buffered recurrence carry
__device__ int            g_cnt;
__device__ volatile int   g_sense;

extern __shared__ float sm[];            // 3*8192 floats = 96 KB dynamic

// --------------------------- grid barrier ----------------------------------
__device__ __forceinline__ void grid_sync(int* lsense) {
    __syncthreads();
    if (threadIdx.x == 0) {
        int s = 1 - *lsense;
        *lsense = s;
        __threadfence();
        if (atomicAdd(&g_cnt, 1) == NBLK - 1) {
            atomicExch(&g_cnt, 0);
            __threadfence();
            g_sense = s;
        } else {
            while (g_sense != s) { __nanosleep(64); }
        }
        __threadfence();
    }
    __syncthreads();
}

// --------------------------- block reduction -------------------------------
__device__ __forceinline__ float blk_sum(float v) {
    __shared__ float red[16];
    #pragma unroll
    for (int o = 16; o; o >>= 1) v += __shfl_xor_sync(0xffffffffu, v, o);
    int w = threadIdx.x >> 5, l = threadIdx.x & 31;
    if (l == 0) red[w] = v;
    __syncthreads();
    if (threadIdx.x < 32) {
        float t = (l < NWB) ? red[l] : 0.f;
        #pragma unroll
        for (int o = 8; o; o >>= 1) t += __shfl_xor_sync(0xffffffffu, t, o);
        if (l == 0) red[0] = t;
    }
    __syncthreads();
    float r = red[0];
    __syncthreads();
    return r;
}

// dst_smem[m] = LN(src)[m] (+ src[m] if addres). Exact two-pass.
__device__ __forceinline__ void stage_ln(const float* __restrict__ src,
                                         const float* __restrict__ gma,
                                         const float* __restrict__ bta,
                                         float* __restrict__ dst,
                                         bool addres) {
    float vals[4];
    float s = 0.f;
    #pragma unroll
    for (int k = 0; k < 4; k++) {
        vals[k] = src[threadIdx.x + k * NTHR];
        s += vals[k];
    }
    float mean = blk_sum(s) * (1.f / (float)MDIM);
    float q = 0.f;
    #pragma unroll
    for (int k = 0; k < 4; k++) {
        float d = vals[k] - mean;
        q += d * d;
    }
    float var  = blk_sum(q) * (1.f / (float)MDIM);
    float rstd = rsqrtf(var + 1e-5f);
    #pragma unroll
    for (int k = 0; k < 4; k++) {
        int m = threadIdx.x + k * NTHR;
        float xn = (vals[k] - mean) * rstd * gma[m] + bta[m];
        dst[m] = addres ? (xn + vals[k]) : xn;
    }
    __syncthreads();
}

// Batched warp dot: one weight row vs NACT x-vectors (x4-stride xs4 apart).
template <int NV4, int NACT>
__device__ __forceinline__ void warp_dotN(const float* __restrict__ w,
                                          const float* __restrict__ xs,
                                          int xs4, int lane,
                                          float* __restrict__ res) {
    const float4* w4 = reinterpret_cast<const float4*>(w);
    const float4* x4 = reinterpret_cast<const float4*>(xs);
    float acc0[NACT], acc1[NACT];
    #pragma unroll
    for (int k = 0; k < NACT; k++) { acc0[k] = 0.f; acc1[k] = 0.f; }
    #pragma unroll 4
    for (int j = 0; j < NV4 / 64; j++) {
        int base = lane + j * 64;
        float4 wa = w4[base];
        float4 wb = w4[base + 32];
        #pragma unroll
        for (int k = 0; k < NACT; k++) {
            float4 xa = x4[k * xs4 + base];
            float4 xb = x4[k * xs4 + base + 32];
            acc0[k] += wa.x * xa.x + wa.y * xa.y + wa.z * xa.z + wa.w * xa.w;
            acc1[k] += wb.x * xb.x + wb.y * xb.y + wb.z * xb.z + wb.w * xb.w;
        }
    }
    #pragma unroll
    for (int k = 0; k < NACT; k++) {
        float a = acc0[k] + acc1[k];
        #pragma unroll
        for (int o = 16; o; o >>= 1) a += __shfl_xor_sync(0xffffffffu, a, o);
        res[k] = a;
    }
}

__global__ void __launch_bounds__(NTHR, 1)
ttm_persistent(const float* __restrict__ x,
               const float* __restrict__ weight,
               const float* __restrict__ Wv,
               const float* __restrict__ Wo,
               const float* __restrict__ ln1_g, const float* __restrict__ ln1_b,
               const float* __restrict__ ln2_g, const float* __restrict__ ln2_b,
               const float* __restrict__ fc1_w, const float* __restrict__ fc1_b,
               const float* __restrict__ fc2_w, const float* __restrict__ fc2_b,
               float* __restrict__ out) {
    const int tid  = threadIdx.x;
    const int lane = tid & 31;
    const int wid  = tid >> 5;
    const int gw   = blockIdx.x * NWB + wid;
    int lsense = 0;

    // zero vcum (both parities) every launch
    for (int g = blockIdx.x * NTHR + tid; g < 2 * NTK * MDIM; g += NBLK * NTHR)
        (&g_vcum[0][0][0])[g] = 0.f;

    // ---- Phase A: segment-average x -> xcfT[m][i] ----
    for (int g = blockIdx.x * NTHR + tid; g < NAVG * MDIM; g += NBLK * NTHR) {
        int i = g & 31;
        int b = (g >> 5) & 127;
        int a = g >> 12;
        const float* p = x + (size_t)a * (128 * 512) + (size_t)b * 512 + i * 16;
        float ssum = 0.f;
        #pragma unroll
        for (int k = 0; k < 16; k++) ssum += p[k];
        g_xcfT[(b * 16 + a) * 32 + i] = ssum * (1.f / 16.f);
    }
    grid_sync(&lsense);   // barrier 1

    // ---- Phase B: s0[i][r] = xcf[i] . weight[r] + bias[i][r] ----
    {
        const int  row = gw;
        const bool has = row < MDIM;
        float acc[32];
        #pragma unroll
        for (int ii = 0; ii < 32; ii++) acc[ii] = 0.f;
        for (int c = 0; c < 8; c++) {
            for (int idx = tid; idx < 8192; idx += NTHR) {
                int mm = idx >> 5, ii = idx & 31;
                sm[mm * 33 + ii] = g_xcfT[(c * 256 + mm) * 32 + ii];
            }
            __syncthreads();
            if (has) {
                const float* wr = weight + (size_t)row * MDIM + c * 256;
                for (int mm = lane; mm < 256; mm += 32) {
                    float w = wr[mm];
                    #pragma unroll
                    for (int ii = 0; ii < 32; ii++)
                        acc[ii] = fmaf(w, sm[mm * 33 + ii], acc[ii]);
                }
            }
            __syncthreads();
        }
        if (has) {
            float myval = 0.f;
            #pragma unroll
            for (int ii = 0; ii < 32; ii++) {
                float v = acc[ii];
                #pragma unroll
                for (int o = 16; o; o >>= 1) v += __shfl_xor_sync(0xffffffffu, v, o);
                if (lane == ii) myval = v;
            }
            int   t    = row >> 1;
            float freq = expf(-(float)t * (4.f / 2048.f) * 9.210340371976184f);
            float ang  = (float)lane * freq;
            float bias = (row & 1) ? cosf(ang) : sinf(ang);
            g_s0[(size_t)lane * MDIM + row] = myval + bias;
        }
    }
    grid_sync(&lsense);   // barrier 2

    // ---- wavefront: 34 stages x 4 barriers ----
    for (int st = 0; st < NST; st++) {
        const int p = st & 1, q = p ^ 1;
        int act_a[3], act_i[3], nact = 0;
        #pragma unroll
        for (int a = 0; a < NTK; a++) {
            int i = st - a;
            if (i >= 0 && i < NAVG) { act_a[nact] = a; act_i[nact] = i; nact++; }
        }
        const int nrows = nact * MDIM;

        // P0: xn_k = LN1(s_in_k) in smem; v_k = Wv[a_k] @ xn_k
        for (int k = 0; k < nact; k++) {
            const float* src = (act_a[k] == 0) ? (g_s0 + (size_t)act_i[k] * MDIM)
                                               : g_sbuf[p][act_a[k]];
            stage_ln(src, ln1_g, ln1_b, sm + k * MDIM, false);
        }
        for (int t = gw; t < nrows; t += NWARPS) {
            int k = t >> 11, r = t & (MDIM - 1);
            const float* W = Wv + ((size_t)act_a[k] * MDIM + r) * MDIM;
            float res[1];
            warp_dotN<512, 1>(W, sm + k * MDIM, 512, lane, res);
            if (lane == 0) g_vv[k][r] = res[0];
        }
        grid_sync(&lsense);

        // P1: u_k = vcum[p][a_k] + v_k (smem); s1_k = Wo[a_k] @ u_k + s_in_k
        for (int k = 0; k < nact; k++) {
            const float* vc = g_vcum[p][act_a[k]];
            for (int m = tid; m < MDIM; m += NTHR)
                sm[k * MDIM + m] = vc[m] + g_vv[k][m];
        }
        __syncthreads();
        if (blockIdx.x < NTK) {
            int a = blockIdx.x, kf = -1;
            for (int k = 0; k < nact; k++) if (act_a[k] == a) kf = k;
            if (kf >= 0)
                for (int m = tid; m < MDIM; m += NTHR)
                    g_vcum[q][a][m] = sm[kf * MDIM + m];
            else
                for (int m = tid; m < MDIM; m += NTHR)
                    g_vcum[q][a][m] = g_vcum[p][a][m];
        }
        for (int t = gw; t < nrows; t += NWARPS) {
            int k = t >> 11, r = t & (MDIM - 1);
            const float* W = Wo + ((size_t)act_a[k] * MDIM + r) * MDIM;
            float res[1];
            warp_dotN<512, 1>(W, sm + k * MDIM, 512, lane, res);
            if (lane == 0) {
                float sin_r = (act_a[k] == 0) ? g_s0[(size_t)act_i[k] * MDIM + r]
                                              : g_sbuf[p][act_a[k]][r];
                g_s1[k][r] = res[0] + sin_r;
            }
        }
        grid_sync(&lsense);

        // P2: s2_k = LN2(s1_k)+s1_k (smem); h_k = gelu(fc1 @ s2_k + b1)
        for (int k = 0; k < nact; k++)
            stage_ln(g_s1[k], ln2_g, ln2_b, sm + k * MDIM, true);
        if (nact == 3) {
            for (int r = gw; r < HDIM; r += NWARPS) {
                float res[3];
                warp_dotN<512, 3>(fc1_w + (size_t)r * MDIM, sm, 512, lane, res);
                if (lane == 0) {
                    float b = fc1_b[r];
                    #pragma unroll
                    for (int k = 0; k < 3; k++) {
                        float xv = res[k] + b;
                        g_hh[k][r] = 0.5f * xv * (1.f + erff(xv * 0.7071067811865476f));
                    }
                }
            }
        } else if (nact == 2) {
            for (int r = gw; r < HDIM; r += NWARPS) {
                float res[2];
                warp_dotN<512, 2>(fc1_w + (size_t)r * MDIM, sm, 512, lane, res);
                if (lane == 0) {
                    float b = fc1_b[r];
                    #pragma unroll
                    for (int k = 0; k < 2; k++) {
                        float xv = res[k] + b;
                        g_hh[k][r] = 0.5f * xv * (1.f + erff(xv * 0.7071067811865476f));
                    }
                }
            }
        } else {
            for (int r = gw; r < HDIM; r += NWARPS) {
                float res[1];
                warp_dotN<512, 1>(fc1_w + (size_t)r * MDIM, sm, 512, lane, res);
                if (lane == 0) {
                    float xv = res[0] + fc1_b[r];
                    g_hh[0][r] = 0.5f * xv * (1.f + erff(xv * 0.7071067811865476f));
                }
            }
        }
        grid_sync(&lsense);

        // P3: stage h_k (smem, 96KB); s_out_k = fc2 @ h_k + b2
        for (int idx = tid; idx < nact * HDIM; idx += NTHR)
            sm[idx] = (&g_hh[0][0])[idx];
        __syncthreads();
        if (gw < MDIM) {
            const int r = gw;
            const float* W = fc2_w + (size_t)r * HDIM;
            float res[3];
            if (nact == 3)      warp_dotN<2048, 3>(W, sm, 2048, lane, res);
            else if (nact == 2) warp_dotN<2048, 2>(W, sm, 2048, lane, res);
            else                warp_dotN<2048, 1>(W, sm, 2048, lane, res);
            if (lane == 0) {
                float b = fc2_b[r];
                for (int k = 0; k < nact; k++) {
                    float val = res[k] + b;
                    int a = act_a[k], i = act_i[k];
                    if (a == NTK - 1) out[(size_t)i * MDIM + r] = val;
                    else              g_sbuf[q][a + 1][r] = val;
                }
            }
        }
        grid_sync(&lsense);
    }
    // barriers: 2 + 34*4 = 138 (EVEN) -> g_sense/g_cnt end at 0.
}

extern "C" void kernel_launch(void* const* d_in, const int* in_sizes, int n_in,
                              void* d_out, int out_size) {
    (void)in_sizes; (void)n_in; (void)out_size;
    const float* x      = (const float*)d_in[0];
    const float* weight = (const float*)d_in[1];
    // d_in[2]=Wq, d_in[3]=Wk : dead (softmax over scalar == 1)
    const float* Wv     = (const float*)d_in[4];
    const float* Wo     = (const float*)d_in[5];
    const float* ln1_g  = (const float*)d_in[6];
    const float* ln1_b  = (const float*)d_in[7];
    const float* ln2_g  = (const float*)d_in[8];
    const float* ln2_b  = (const float*)d_in[9];
    const float* fc1_w  = (const float*)d_in[10];
    const float* fc1_b  = (const float*)d_in[11];
    const float* fc2_w  = (const float*)d_in[12];
    const float* fc2_b  = (const float*)d_in[13];

    const int smem_bytes = NTK * HDIM * sizeof(float);   // 96 KB
    cudaFuncSetAttribute(ttm_persistent,
                         cudaFuncAttributeMaxDynamicSharedMemorySize, smem_bytes);
    ttm_persistent<<<NBLK, NTHR, smem_bytes>>>(x, weight, Wv, Wo,
                                               ln1_g, ln1_b, ln2_g, ln2_b,
                                               fc1_w, fc1_b, fc2_w, fc2_b,
                                               (float*)d_out);
}